// round 1
// baseline (speedup 1.0000x reference)
#include <cuda_runtime.h>
#include <math.h>

#define B_   64
#define T_   256
#define W_   20
#define NP   6
#define NT   12
#define CC   32
#define FD   8
#define PR   64
#define NW   (B_*T_)      // 16384 windows
#define L1N  18           // conv1 output length
#define L2N  16           // conv2 output length

// xg scratch: (B*T, 4*PROJ) = 16384 x 256 floats (16.8 MB) — static device array (no allocs)
__device__ float g_xg[NW * 4 * PR];

// ---------------------------------------------------------------------------
// Kernel A: encoders + fragility + projection + xg precompute
// grid-strided over windows; one window processed by all 512 threads.
// ---------------------------------------------------------------------------
#define SMEM_FLOATS 30976

__global__ __launch_bounds__(512) void encode_kernel(
    const float* __restrict__ pressure, const float* __restrict__ torque,
    const float* __restrict__ frag,
    const float* __restrict__ pw1, const float* __restrict__ pb1,
    const float* __restrict__ pw2, const float* __restrict__ pb2,
    const float* __restrict__ tw1, const float* __restrict__ tb1,
    const float* __restrict__ tw2, const float* __restrict__ tb2,
    const float* __restrict__ fw,  const float* __restrict__ fb,
    const float* __restrict__ prw, const float* __restrict__ prb,
    const float* __restrict__ Wih, const float* __restrict__ bih,
    const float* __restrict__ bhh)
{
    extern __shared__ float s[];
    float* s_pw1  = s;                 // 576   [32][6][3]
    float* s_pb1  = s_pw1  + 576;      // 32
    float* s_pw2  = s_pb1  + 32;       // 3072  [32][32][3]
    float* s_pb2  = s_pw2  + 3072;     // 32
    float* s_tw1  = s_pb2  + 32;       // 1152  [32][12][3]
    float* s_tb1  = s_tw1  + 1152;     // 32
    float* s_tw2  = s_tb1  + 32;       // 3072
    float* s_tb2  = s_tw2  + 3072;     // 32
    float* s_prwT = s_tb2  + 32;       // 4608  [72][64]  (transposed)
    float* s_prb  = s_prwT + 4608;     // 64
    float* s_WihT = s_prb  + 64;       // 16384 [64][256] (transposed)
    float* s_bsum = s_WihT + 16384;    // 256   bih+bhh
    float* s_fw   = s_bsum + 256;      // 8
    float* s_fb   = s_fw   + 8;        // 8
    float* s_xp   = s_fb   + 8;        // 120   window pressure [w][c]
    float* s_xt   = s_xp   + 120;      // 240   window torque   [w][c]
    float* s_h1p  = s_xt   + 240;      // 576   [32][18]
    float* s_h1t  = s_h1p  + 576;      // 576
    float* s_cat  = s_h1t  + 576;      // 72
    float* s_feat = s_cat  + 72;       // 64

    const int tid = threadIdx.x;

    // ---- load weights (once per CTA) ----
    for (int i = tid; i < 576;  i += 512) s_pw1[i] = pw1[i];
    for (int i = tid; i < 1152; i += 512) s_tw1[i] = tw1[i];
    for (int i = tid; i < 3072; i += 512) { s_pw2[i] = pw2[i]; s_tw2[i] = tw2[i]; }
    for (int i = tid; i < 32;   i += 512) {
        s_pb1[i] = pb1[i]; s_pb2[i] = pb2[i]; s_tb1[i] = tb1[i]; s_tb2[i] = tb2[i];
    }
    for (int i = tid; i < 4608; i += 512) {       // prwT[j][o] = prw[o][j]
        int j = i >> 6, o = i & 63;
        s_prwT[i] = prw[o * 72 + j];
    }
    for (int i = tid; i < 64;   i += 512) s_prb[i] = prb[i];
    for (int i = tid; i < 16384; i += 512) {      // WihT[h][g] = Wih[g][h]
        int h = i >> 8, g = i & 255;
        s_WihT[i] = Wih[g * 64 + h];
    }
    for (int i = tid; i < 256;  i += 512) s_bsum[i] = bih[i] + bhh[i];
    if (tid < 8) { s_fw[tid] = fw[tid]; s_fb[tid] = fb[tid]; }
    __syncthreads();

    for (int win = blockIdx.x; win < NW; win += gridDim.x) {
        const int b = win >> 8;    // T_ = 256
        const float* pwin = pressure + (size_t)win * (W_ * NP);
        const float* twin = torque   + (size_t)win * (W_ * NT);

        // ---- stage 1: load window ----
        for (int i = tid; i < 120; i += 512) s_xp[i] = pwin[i];
        for (int i = tid; i < 240; i += 512) s_xt[i] = twin[i];
        __syncthreads();

        // ---- stage 2: conv1 (both encoders), relu ----
        for (int oi = tid; oi < 1152; oi += 512) {
            if (oi < 576) {
                int o = oi / 18, l = oi - o * 18;
                float acc = s_pb1[o];
                const float* wrow = s_pw1 + o * 18;   // [6][3]
                #pragma unroll
                for (int i = 0; i < 6; i++)
                    #pragma unroll
                    for (int k = 0; k < 3; k++)
                        acc += wrow[i * 3 + k] * s_xp[(l + k) * NP + i];
                s_h1p[o * 18 + l] = fmaxf(acc, 0.f);
            } else {
                int oj = oi - 576;
                int o = oj / 18, l = oj - o * 18;
                float acc = s_tb1[o];
                const float* wrow = s_tw1 + o * 36;   // [12][3]
                #pragma unroll
                for (int i = 0; i < 12; i++)
                    #pragma unroll
                    for (int k = 0; k < 3; k++)
                        acc += wrow[i * 3 + k] * s_xt[(l + k) * NT + i];
                s_h1t[o * 18 + l] = fmaxf(acc, 0.f);
            }
        }
        __syncthreads();

        // ---- stage 3: conv2 + relu + mean pool (shfl reduce over 16 lanes) ----
        #pragma unroll
        for (int rep = 0; rep < 2; rep++) {
            int oi  = tid + rep * 512;
            int enc = oi >> 9;         // 0 = pressure, 1 = torque
            int rem = oi & 511;
            int o = rem >> 4, l = rem & 15;
            const float* w2 = enc ? s_tw2 : s_pw2;
            const float* h1 = enc ? s_h1t : s_h1p;
            float acc = enc ? s_tb2[o] : s_pb2[o];
            const float* wrow = w2 + o * 96;
            #pragma unroll
            for (int i = 0; i < 32; i++) {
                const float* hrow = h1 + i * 18 + l;
                acc += wrow[i * 3] * hrow[0] + wrow[i * 3 + 1] * hrow[1]
                     + wrow[i * 3 + 2] * hrow[2];
            }
            float v = fmaxf(acc, 0.f) * (1.f / 16.f);
            #pragma unroll
            for (int off = 8; off; off >>= 1)
                v += __shfl_down_sync(0xffffffffu, v, off, 16);
            if ((tid & 15) == 0) s_cat[enc * 32 + o] = v;
        }
        if (tid < 8) s_cat[64 + tid] = fmaxf(frag[b] * s_fw[tid] + s_fb[tid], 0.f);
        __syncthreads();

        // ---- stage 4: projection, relu ----
        if (tid < 64) {
            float acc = s_prb[tid];
            #pragma unroll
            for (int j = 0; j < 72; j++)
                acc += s_prwT[j * 64 + tid] * s_cat[j];
            s_feat[tid] = fmaxf(acc, 0.f);
        }
        __syncthreads();

        // ---- stage 5: xg = feat @ Wih.T + bih + bhh ----
        if (tid < 256) {
            float acc = s_bsum[tid];
            #pragma unroll
            for (int h = 0; h < 64; h++)
                acc += s_WihT[h * 256 + tid] * s_feat[h];
            g_xg[(size_t)win * 256 + tid] = acc;
        }
        __syncthreads();
    }
}

// ---------------------------------------------------------------------------
// Kernel B: per-batch LSTM + head. One CTA per batch element.
// Whh row j lives in thread j's registers; h broadcast from smem.
// ---------------------------------------------------------------------------
__device__ __forceinline__ float sigf(float x) { return 1.f / (1.f + expf(-x)); }

__global__ __launch_bounds__(256) void lstm_kernel(
    const float* __restrict__ Whh, const float* __restrict__ hw,
    const float* __restrict__ hb, float* __restrict__ out)
{
    __shared__ float h_s[64];
    __shared__ float gates[256];
    __shared__ float s_hw[256];
    __shared__ float s_hb[4];

    const int b = blockIdx.x;
    const int j = threadIdx.x;

    // Whh row j -> registers (16 x float4)
    float4 wv[16];
    const float4* wr = reinterpret_cast<const float4*>(Whh + j * 64);
    #pragma unroll
    for (int q = 0; q < 16; q++) wv[q] = wr[q];

    if (j < 256) s_hw[j] = hw[j];      // hw is 4*64 = 256
    if (j < 4)   s_hb[j] = hb[j];
    if (j < 64)  h_s[j] = 0.f;
    float c = 0.f;

    const float* xg = g_xg + (size_t)b * T_ * 256;
    float xg_cur = xg[j];
    __syncthreads();

    for (int t = 0; t < T_; t++) {
        float xg_next = (t + 1 < T_) ? xg[(size_t)(t + 1) * 256 + j] : 0.f;

        float acc = xg_cur;
        const float4* h4 = reinterpret_cast<const float4*>(h_s);
        #pragma unroll
        for (int q = 0; q < 16; q++) {
            float4 hh = h4[q];
            acc += wv[q].x * hh.x + wv[q].y * hh.y
                 + wv[q].z * hh.z + wv[q].w * hh.w;
        }
        gates[j] = acc;
        xg_cur = xg_next;
        __syncthreads();

        if (j < 64) {
            float gi = gates[j], gf = gates[64 + j], gg = gates[128 + j], go = gates[192 + j];
            c = sigf(gf) * c + sigf(gi) * tanhf(gg);
            h_s[j] = sigf(go) * tanhf(c);
        }
        __syncthreads();

        if (j < 4) {   // head: out[b][t][j] = sigmoid(h . hw[j] + hb[j])
            float a2 = s_hb[j];
            #pragma unroll
            for (int h = 0; h < 64; h++) a2 += s_hw[j * 64 + h] * h_s[h];
            out[((size_t)b * T_ + t) * 4 + j] = sigf(a2);
        }
    }

    if (j < 64) {
        out[(size_t)B_ * T_ * 4 + b * 64 + j] = h_s[j];                 // hT
        out[(size_t)B_ * T_ * 4 + B_ * 64 + b * 64 + j] = c;            // cT
    }
}

// ---------------------------------------------------------------------------
extern "C" void kernel_launch(void* const* d_in, const int* in_sizes, int n_in,
                              void* d_out, int out_size)
{
    const float* pressure = (const float*)d_in[0];
    const float* torque   = (const float*)d_in[1];
    const float* frag     = (const float*)d_in[2];
    const float* pw1 = (const float*)d_in[3];
    const float* pb1 = (const float*)d_in[4];
    const float* pw2 = (const float*)d_in[5];
    const float* pb2 = (const float*)d_in[6];
    const float* tw1 = (const float*)d_in[7];
    const float* tb1 = (const float*)d_in[8];
    const float* tw2 = (const float*)d_in[9];
    const float* tb2 = (const float*)d_in[10];
    const float* fw  = (const float*)d_in[11];
    const float* fb  = (const float*)d_in[12];
    const float* prw = (const float*)d_in[13];
    const float* prb = (const float*)d_in[14];
    const float* Wih = (const float*)d_in[15];
    const float* Whh = (const float*)d_in[16];
    const float* bih = (const float*)d_in[17];
    const float* bhh = (const float*)d_in[18];
    const float* hw  = (const float*)d_in[19];
    const float* hb  = (const float*)d_in[20];

    const int smem_bytes = SMEM_FLOATS * sizeof(float);   // 123904 B
    cudaFuncSetAttribute(encode_kernel,
                         cudaFuncAttributeMaxDynamicSharedMemorySize, smem_bytes);

    encode_kernel<<<152, 512, smem_bytes>>>(
        pressure, torque, frag,
        pw1, pb1, pw2, pb2, tw1, tb1, tw2, tb2,
        fw, fb, prw, prb, Wih, bih, bhh);

    lstm_kernel<<<B_, 256>>>(Whh, hw, hb, (float*)d_out);
}

// round 2
// speedup vs baseline: 2.5921x; 2.5921x over previous
#include <cuda_runtime.h>
#include <math.h>

#define B_   64
#define T_   256
#define W_   20
#define NP   6
#define NT   12
#define CC   32
#define FD   8
#define PR   64
#define NW   (B_*T_)      // 16384 windows
#define WB   8            // windows per CTA iteration
#define NCHUNK (NW / WB)  // 2048

// scratch (static device arrays — no allocs)
__device__ float g_xg[NW * 4 * PR];   // 16.8 MB: precomputed input gates
__device__ float g_h [NW * PR];      // 4.2 MB: per-step hidden states

// ---------------------------------------------------------------------------
// packed f32x2 fma
// ---------------------------------------------------------------------------
__device__ __forceinline__ unsigned long long fma2(unsigned long long a,
                                                   unsigned long long b,
                                                   unsigned long long c) {
    unsigned long long d;
    asm("fma.rn.f32x2 %0, %1, %2, %3;" : "=l"(d) : "l"(a), "l"(b), "l"(c));
    return d;
}
__device__ __forceinline__ float2 u2f2(unsigned long long v) {
    float2 r;
    asm("mov.b64 {%0, %1}, %2;" : "=f"(r.x), "=f"(r.y) : "l"(v));
    return r;
}
__device__ __forceinline__ float sigf(float x) {
    return __fdividef(1.f, 1.f + __expf(-x));
}
__device__ __forceinline__ float tanhfast(float x) {
    float e = __expf(-2.f * x);
    return __fdividef(1.f - e, 1.f + e);
}

// ---------------------------------------------------------------------------
// smem layout for encode (floats)
// ---------------------------------------------------------------------------
#define OFF_W1P   0                    // [6][32][4]   conv1-p weights [i][o][k(pad4)]
#define OFF_W1T   (OFF_W1P + 768)      // [12][32][4]
#define OFF_B1P   (OFF_W1T + 1536)     // 32
#define OFF_B1T   (OFF_B1P + 32)       // 32
#define OFF_W2P   (OFF_B1T + 32)       // [2][32][32][4] conv2 weights [enc][i][o][k]
#define OFF_B2    (OFF_W2P + 8192)     // [2][32]
#define OFF_PRWT  (OFF_B2  + 64)       // [72][64]
#define OFF_PRB   (OFF_PRWT+ 4608)     // 64
#define OFF_WIHT  (OFF_PRB + 64)       // [64][256]
#define OFF_BSUM  (OFF_WIHT+ 16384)    // 256
#define OFF_FW    (OFF_BSUM+ 256)      // 8
#define OFF_FB    (OFF_FW  + 8)        // 8
#define OFF_XP    (OFF_FB  + 8)        // [8][6][20]  = 960
#define OFF_XT    (OFF_XP  + 960)      // [8][12][20] = 1920
#define OFF_H1    (OFF_XT  + 1920)     // [8][2][32][20] = 10240
#define OFF_CAT   (OFF_H1  + 10240)    // [8][80] = 640  (72 used)
#define OFF_FEAT  (OFF_CAT + 640)      // [8][64] = 512
#define SMEM_FLOATS (OFF_FEAT + 512)   // 46224 floats = 184896 B

// ---------------------------------------------------------------------------
// Kernel A: encoders + fragility + projection + xg precompute
// 8 windows per CTA iteration; thread -> (window, encoder, channel)
// ---------------------------------------------------------------------------
__global__ __launch_bounds__(512) void encode_kernel(
    const float* __restrict__ pressure, const float* __restrict__ torque,
    const float* __restrict__ frag,
    const float* __restrict__ pw1, const float* __restrict__ pb1,
    const float* __restrict__ pw2, const float* __restrict__ pb2,
    const float* __restrict__ tw1, const float* __restrict__ tb1,
    const float* __restrict__ tw2, const float* __restrict__ tb2,
    const float* __restrict__ fw,  const float* __restrict__ fb,
    const float* __restrict__ prw, const float* __restrict__ prb,
    const float* __restrict__ Wih, const float* __restrict__ bih,
    const float* __restrict__ bhh)
{
    extern __shared__ float s[];
    const int tid = threadIdx.x;

    // ---- weight staging (transposed for conflict-free reads) ----
    for (int i = tid; i < 576; i += 512) {              // pw1[o][ci][k]
        int o = i / 18, r = i - o * 18, ci = r / 3, k = r - ci * 3;
        s[OFF_W1P + (ci * 32 + o) * 4 + k] = pw1[i];
    }
    for (int i = tid; i < 1152; i += 512) {             // tw1[o][ci][k]
        int o = i / 36, r = i - o * 36, ci = r / 3, k = r - ci * 3;
        s[OFF_W1T + (ci * 32 + o) * 4 + k] = tw1[i];
    }
    for (int i = tid; i < 3072; i += 512) {             // pw2/tw2 [o][ci][k]
        int o = i / 96, r = i - o * 96, ci = r / 3, k = r - ci * 3;
        s[OFF_W2P +        (ci * 32 + o) * 4 + k] = pw2[i];
        s[OFF_W2P + 4096 + (ci * 32 + o) * 4 + k] = tw2[i];
    }
    for (int i = tid; i < 32; i += 512) {
        s[OFF_B1P + i] = pb1[i]; s[OFF_B1T + i] = tb1[i];
        s[OFF_B2  + i] = pb2[i]; s[OFF_B2 + 32 + i] = tb2[i];
    }
    for (int i = tid; i < 4608; i += 512) {             // prwT[j][o] = prw[o][j]
        int j = i >> 6, o = i & 63;
        s[OFF_PRWT + i] = prw[o * 72 + j];
    }
    for (int i = tid; i < 64; i += 512) s[OFF_PRB + i] = prb[i];
    for (int i = tid; i < 16384; i += 512) {            // WihT[h][g] = Wih[g][h]
        int h = i >> 8, g = i & 255;
        s[OFF_WIHT + i] = Wih[g * 64 + h];
    }
    for (int i = tid; i < 256; i += 512) s[OFF_BSUM + i] = bih[i] + bhh[i];
    if (tid < 8) { s[OFF_FW + tid] = fw[tid]; s[OFF_FB + tid] = fb[tid]; }
    __syncthreads();

    const int wid = tid >> 5, lane = tid & 31;
    const int wn = wid & 7, enc = wid >> 3;   // warp-homogeneous (win, enc)

    for (int chunk = blockIdx.x; chunk < NCHUNK; chunk += gridDim.x) {
        const int win0 = chunk * WB;
        const int b0 = win0 >> 8;             // all 8 windows share batch index

        // ---- stage 1: load + transpose inputs (coalesced LDG) ----
        {
            const float* pg = pressure + (size_t)win0 * 120;
            for (int i = tid; i < 960; i += 512) {
                int w8 = i / 120, r = i - w8 * 120, w = r / 6, c = r - w * 6;
                s[OFF_XP + w8 * 120 + c * 20 + w] = pg[i];
            }
            const float* tg = torque + (size_t)win0 * 240;
            for (int i = tid; i < 1920; i += 512) {
                int w8 = i / 240, r = i - w8 * 240, w = r / 12, c = r - w * 12;
                s[OFF_XT + w8 * 240 + c * 20 + w] = tg[i];
            }
        }
        __syncthreads();

        // ---- stage 2: conv1 + relu (registers; one thread = one out-channel) ----
        {
            const int o = lane;
            float acc[18];
            if (enc == 0) {
                #pragma unroll
                for (int l = 0; l < 18; l++) acc[l] = s[OFF_B1P + o];
                const float* xb = s + OFF_XP + wn * 120;
                #pragma unroll
                for (int ci = 0; ci < 6; ci++) {
                    float4 w = *(const float4*)(s + OFF_W1P + (ci * 32 + o) * 4);
                    float x[20];
                    #pragma unroll
                    for (int q = 0; q < 5; q++) {
                        float4 v = *(const float4*)(xb + ci * 20 + q * 4);
                        x[q*4] = v.x; x[q*4+1] = v.y; x[q*4+2] = v.z; x[q*4+3] = v.w;
                    }
                    #pragma unroll
                    for (int l = 0; l < 18; l++)
                        acc[l] += w.x * x[l] + w.y * x[l+1] + w.z * x[l+2];
                }
            } else {
                #pragma unroll
                for (int l = 0; l < 18; l++) acc[l] = s[OFF_B1T + o];
                const float* xb = s + OFF_XT + wn * 240;
                #pragma unroll
                for (int ci = 0; ci < 12; ci++) {
                    float4 w = *(const float4*)(s + OFF_W1T + (ci * 32 + o) * 4);
                    float x[20];
                    #pragma unroll
                    for (int q = 0; q < 5; q++) {
                        float4 v = *(const float4*)(xb + ci * 20 + q * 4);
                        x[q*4] = v.x; x[q*4+1] = v.y; x[q*4+2] = v.z; x[q*4+3] = v.w;
                    }
                    #pragma unroll
                    for (int l = 0; l < 18; l++)
                        acc[l] += w.x * x[l] + w.y * x[l+1] + w.z * x[l+2];
                }
            }
            float* hb = s + OFF_H1 + wn * 1280 + enc * 640 + o * 20;
            #pragma unroll
            for (int l = 0; l < 18; l += 2) {
                float2 v;
                v.x = fmaxf(acc[l],   0.f);
                v.y = fmaxf(acc[l+1], 0.f);
                *(float2*)(hb + l) = v;
            }
        }
        __syncthreads();

        // ---- stage 3: conv2 + relu + mean pool (registers, broadcast h1) ----
        {
            const int o = lane;
            float acc[16];
            #pragma unroll
            for (int l = 0; l < 16; l++) acc[l] = s[OFF_B2 + enc * 32 + o];
            const float* hbase = s + OFF_H1 + wn * 1280 + enc * 640;
            const float* wbase = s + OFF_W2P + enc * 4096;
            #pragma unroll 4
            for (int ci = 0; ci < 32; ci++) {
                float4 w = *(const float4*)(wbase + (ci * 32 + o) * 4);
                const float* hr = hbase + ci * 20;
                float x[18];
                #pragma unroll
                for (int q = 0; q < 4; q++) {
                    float4 v = *(const float4*)(hr + q * 4);
                    x[q*4] = v.x; x[q*4+1] = v.y; x[q*4+2] = v.z; x[q*4+3] = v.w;
                }
                { float2 v = *(const float2*)(hr + 16); x[16] = v.x; x[17] = v.y; }
                #pragma unroll
                for (int l = 0; l < 16; l++)
                    acc[l] += w.x * x[l] + w.y * x[l+1] + w.z * x[l+2];
            }
            float pool = 0.f;
            #pragma unroll
            for (int l = 0; l < 16; l++) pool += fmaxf(acc[l], 0.f);
            s[OFF_CAT + wn * 80 + enc * 32 + o] = pool * (1.f / 16.f);
        }
        if (tid < 64) {   // fragility features
            int w8 = tid >> 3, k = tid & 7;
            s[OFF_CAT + w8 * 80 + 64 + k] =
                fmaxf(frag[b0] * s[OFF_FW + k] + s[OFF_FB + k], 0.f);
        }
        __syncthreads();

        // ---- stage 4: projection + relu ----
        {
            const int w8 = tid >> 6, o = tid & 63;
            float acc = s[OFF_PRB + o];
            const float* cat = s + OFF_CAT + w8 * 80;
            #pragma unroll
            for (int j = 0; j < 72; j++)
                acc += s[OFF_PRWT + j * 64 + o] * cat[j];
            s[OFF_FEAT + w8 * 64 + o] = fmaxf(acc, 0.f);
        }
        __syncthreads();

        // ---- stage 5: xg = feat @ Wih.T + bih + bhh -> global ----
        {
            const int w8 = tid >> 6, g0 = (tid & 63) * 4;
            const float* ft = s + OFF_FEAT + w8 * 64;
            float4 acc = *(const float4*)(s + OFF_BSUM + g0);
            #pragma unroll
            for (int h = 0; h < 64; h++) {
                float f = ft[h];
                float4 w = *(const float4*)(s + OFF_WIHT + h * 256 + g0);
                acc.x += w.x * f; acc.y += w.y * f;
                acc.z += w.z * f; acc.w += w.w * f;
            }
            *(float4*)(g_xg + (size_t)(win0 + w8) * 256 + g0) = acc;
        }
        __syncthreads();
    }
}

// ---------------------------------------------------------------------------
// Kernel B: per-batch LSTM. One CTA per batch; head deferred to kernel C.
// ---------------------------------------------------------------------------
__global__ __launch_bounds__(256) void lstm_kernel(
    const float* __restrict__ Whh, float* __restrict__ out)
{
    __shared__ __align__(16) float h_s[64];
    __shared__ float gates[256];

    const int b = blockIdx.x;
    const int j = threadIdx.x;

    // Whh row j -> registers as 16 x (2 packed f32x2)
    ulonglong2 wv[16];
    const ulonglong2* wr = reinterpret_cast<const ulonglong2*>(Whh + j * 64);
    #pragma unroll
    for (int q = 0; q < 16; q++) wv[q] = wr[q];

    if (j < 64) h_s[j] = 0.f;
    float c = 0.f;

    const float* xg = g_xg + (size_t)b * T_ * 256;
    float xcur = xg[j];
    __syncthreads();

    for (int t = 0; t < T_; t++) {
        float xnext = (t + 1 < T_) ? xg[(size_t)(t + 1) * 256 + j] : 0.f;

        unsigned long long a0 = 0ull, a1 = 0ull;   // two independent FFMA2 chains
        const ulonglong2* h2 = reinterpret_cast<const ulonglong2*>(h_s);
        #pragma unroll
        for (int q = 0; q < 16; q++) {
            ulonglong2 hh = h2[q];
            a0 = fma2(wv[q].x, hh.x, a0);
            a1 = fma2(wv[q].y, hh.y, a1);
        }
        float2 p0 = u2f2(a0), p1 = u2f2(a1);
        gates[j] = xcur + (p0.x + p0.y) + (p1.x + p1.y);
        xcur = xnext;
        __syncthreads();

        if (j < 64) {
            float gi = gates[j],       gf = gates[64 + j];
            float gg = gates[128 + j], go = gates[192 + j];
            c = sigf(gf) * c + sigf(gi) * tanhfast(gg);
            float h = sigf(go) * tanhfast(c);
            h_s[j] = h;
            g_h[((size_t)b * T_ + t) * 64 + j] = h;
        }
        __syncthreads();
    }

    if (j < 64) {
        out[(size_t)B_ * T_ * 4 + b * 64 + j] = h_s[j];                 // hT
        out[(size_t)B_ * T_ * 4 + B_ * 64 + b * 64 + j] = c;            // cT
    }
}

// ---------------------------------------------------------------------------
// Kernel C: head — out[b][t][o] = sigmoid(h . hw[o] + hb[o]), fully parallel
// ---------------------------------------------------------------------------
__global__ __launch_bounds__(256) void head_kernel(
    const float* __restrict__ hw, const float* __restrict__ hb,
    float* __restrict__ out)
{
    __shared__ float s_hw[256];
    __shared__ float s_hb[4];
    const int tid = threadIdx.x;
    s_hw[tid] = hw[tid];
    if (tid < 4) s_hb[tid] = hb[tid];
    __syncthreads();

    const int bt = blockIdx.x * 256 + tid;   // grid 64 x 256 = 16384
    const float4* h4 = reinterpret_cast<const float4*>(g_h + (size_t)bt * 64);
    float a0 = s_hb[0], a1 = s_hb[1], a2 = s_hb[2], a3 = s_hb[3];
    #pragma unroll
    for (int q = 0; q < 16; q++) {
        float4 hv = h4[q];
        a0 += s_hw[      q*4]*hv.x + s_hw[      q*4+1]*hv.y + s_hw[      q*4+2]*hv.z + s_hw[      q*4+3]*hv.w;
        a1 += s_hw[ 64 + q*4]*hv.x + s_hw[ 64 + q*4+1]*hv.y + s_hw[ 64 + q*4+2]*hv.z + s_hw[ 64 + q*4+3]*hv.w;
        a2 += s_hw[128 + q*4]*hv.x + s_hw[128 + q*4+1]*hv.y + s_hw[128 + q*4+2]*hv.z + s_hw[128 + q*4+3]*hv.w;
        a3 += s_hw[192 + q*4]*hv.x + s_hw[192 + q*4+1]*hv.y + s_hw[192 + q*4+2]*hv.z + s_hw[192 + q*4+3]*hv.w;
    }
    float4 r;
    r.x = sigf(a0); r.y = sigf(a1); r.z = sigf(a2); r.w = sigf(a3);
    *reinterpret_cast<float4*>(out + (size_t)bt * 4) = r;
}

// ---------------------------------------------------------------------------
extern "C" void kernel_launch(void* const* d_in, const int* in_sizes, int n_in,
                              void* d_out, int out_size)
{
    const float* pressure = (const float*)d_in[0];
    const float* torque   = (const float*)d_in[1];
    const float* frag     = (const float*)d_in[2];
    const float* pw1 = (const float*)d_in[3];
    const float* pb1 = (const float*)d_in[4];
    const float* pw2 = (const float*)d_in[5];
    const float* pb2 = (const float*)d_in[6];
    const float* tw1 = (const float*)d_in[7];
    const float* tb1 = (const float*)d_in[8];
    const float* tw2 = (const float*)d_in[9];
    const float* tb2 = (const float*)d_in[10];
    const float* fw  = (const float*)d_in[11];
    const float* fb  = (const float*)d_in[12];
    const float* prw = (const float*)d_in[13];
    const float* prb = (const float*)d_in[14];
    const float* Wih = (const float*)d_in[15];
    const float* Whh = (const float*)d_in[16];
    const float* bih = (const float*)d_in[17];
    const float* bhh = (const float*)d_in[18];
    const float* hw  = (const float*)d_in[19];
    const float* hb  = (const float*)d_in[20];

    const int smem_bytes = SMEM_FLOATS * sizeof(float);   // 184896 B
    static int configured = 0;
    cudaFuncSetAttribute(encode_kernel,
                         cudaFuncAttributeMaxDynamicSharedMemorySize, smem_bytes);
    (void)configured;

    encode_kernel<<<152, 512, smem_bytes>>>(
        pressure, torque, frag,
        pw1, pb1, pw2, pb2, tw1, tb1, tw2, tb2,
        fw, fb, prw, prb, Wih, bih, bhh);

    lstm_kernel<<<B_, 256>>>(Whh, (float*)d_out);
    head_kernel<<<64, 256>>>(hw, hb, (float*)d_out);
}

// round 3
// speedup vs baseline: 3.0391x; 1.1724x over previous
#include <cuda_runtime.h>
#include <math.h>

#define B_   64
#define T_   256
#define W_   20
#define NP   6
#define NT   12
#define CC   32
#define FD   8
#define PR   64
#define NW   (B_*T_)      // 16384 windows
#define WB   8            // windows per CTA iteration
#define NCHUNK (NW / WB)  // 2048

// scratch (static device arrays — no allocs)
__device__ float g_xg[NW * 4 * PR];   // 16.8 MB: precomputed input gates
__device__ float g_h [NW * PR];       // 4.2 MB: per-step hidden states
__device__ float g_prwT[72 * 64];     // projection weights, transposed
__device__ float g_WihT[64 * 256];    // Wih transposed [h][g]
__device__ float g_bsum[256];         // bih + bhh

// ---------------------------------------------------------------------------
// fast math helpers
// ---------------------------------------------------------------------------
__device__ __forceinline__ unsigned long long fma2(unsigned long long a,
                                                   unsigned long long b,
                                                   unsigned long long c) {
    unsigned long long d;
    asm("fma.rn.f32x2 %0, %1, %2, %3;" : "=l"(d) : "l"(a), "l"(b), "l"(c));
    return d;
}
__device__ __forceinline__ float2 u2f2(unsigned long long v) {
    float2 r;
    asm("mov.b64 {%0, %1}, %2;" : "=f"(r.x), "=f"(r.y) : "l"(v));
    return r;
}
__device__ __forceinline__ float tanha(float x) {
    float y;
    asm("tanh.approx.f32 %0, %1;" : "=f"(y) : "f"(x));
    return y;
}
__device__ __forceinline__ float siga(float x) {
    return fmaf(tanha(0.5f * x), 0.5f, 0.5f);
}

// ---------------------------------------------------------------------------
// smem layout for encode (floats) — 24912 floats = 99648 B  (2 CTAs/SM)
// ---------------------------------------------------------------------------
#define OFF_W1P   0                    // [6][32][4]
#define OFF_W1T   (OFF_W1P + 768)      // [12][32][4]
#define OFF_B1P   (OFF_W1T + 1536)     // 32
#define OFF_B1T   (OFF_B1P + 32)       // 32
#define OFF_W2P   (OFF_B1T + 32)       // [2][32][32][4]
#define OFF_B2    (OFF_W2P + 8192)     // [2][32]
#define OFF_FW    (OFF_B2  + 64)       // 8
#define OFF_FB    (OFF_FW  + 8)        // 8
#define OFF_XP    (OFF_FB  + 8)        // [8][6][20]
#define OFF_XT    (OFF_XP  + 960)      // [8][12][20]
#define OFF_H1    (OFF_XT  + 1920)     // [8][2][32][20]
#define OFF_CAT   (OFF_H1  + 10240)    // [8][80]
#define OFF_FEAT  (OFF_CAT + 640)      // [8][64]
#define SMEM_FLOATS (OFF_FEAT + 512)

// ---------------------------------------------------------------------------
// Kernel 0: weight transposes (deterministic, every launch)
// ---------------------------------------------------------------------------
__global__ __launch_bounds__(256) void init_kernel(
    const float* __restrict__ prw, const float* __restrict__ Wih,
    const float* __restrict__ bih, const float* __restrict__ bhh)
{
    int i = blockIdx.x * 256 + threadIdx.x;   // grid 64 x 256
    if (i < 4608) { int j = i >> 6, o = i & 63; g_prwT[i] = prw[o * 72 + j]; }
    if (i < 16384) { int h = i >> 8, g = i & 255; g_WihT[i] = Wih[g * 64 + h]; }
    if (i < 256) g_bsum[i] = bih[i] + bhh[i];
}

// ---------------------------------------------------------------------------
// Kernel A: encoders + fragility + projection + xg precompute
// ---------------------------------------------------------------------------
__global__ __launch_bounds__(512, 2) void encode_kernel(
    const float* __restrict__ pressure, const float* __restrict__ torque,
    const float* __restrict__ frag,
    const float* __restrict__ pw1, const float* __restrict__ pb1,
    const float* __restrict__ pw2, const float* __restrict__ pb2,
    const float* __restrict__ tw1, const float* __restrict__ tb1,
    const float* __restrict__ tw2, const float* __restrict__ tb2,
    const float* __restrict__ fw,  const float* __restrict__ fb,
    const float* __restrict__ prb)
{
    extern __shared__ float s[];
    const int tid = threadIdx.x;

    // ---- weight staging ----
    for (int i = tid; i < 576; i += 512) {              // pw1[o][ci][k]
        int o = i / 18, r = i - o * 18, ci = r / 3, k = r - ci * 3;
        s[OFF_W1P + (ci * 32 + o) * 4 + k] = pw1[i];
    }
    for (int i = tid; i < 1152; i += 512) {             // tw1[o][ci][k]
        int o = i / 36, r = i - o * 36, ci = r / 3, k = r - ci * 3;
        s[OFF_W1T + (ci * 32 + o) * 4 + k] = tw1[i];
    }
    for (int i = tid; i < 3072; i += 512) {             // pw2/tw2 [o][ci][k]
        int o = i / 96, r = i - o * 96, ci = r / 3, k = r - ci * 3;
        s[OFF_W2P +        (ci * 32 + o) * 4 + k] = pw2[i];
        s[OFF_W2P + 4096 + (ci * 32 + o) * 4 + k] = tw2[i];
    }
    for (int i = tid; i < 32; i += 512) {
        s[OFF_B1P + i] = pb1[i]; s[OFF_B1T + i] = tb1[i];
        s[OFF_B2  + i] = pb2[i]; s[OFF_B2 + 32 + i] = tb2[i];
    }
    if (tid < 8) { s[OFF_FW + tid] = fw[tid]; s[OFF_FB + tid] = fb[tid]; }
    __syncthreads();

    const int wid = tid >> 5, lane = tid & 31;
    const int wn = wid & 7, enc = wid >> 3;

    for (int chunk = blockIdx.x; chunk < NCHUNK; chunk += gridDim.x) {
        const int win0 = chunk * WB;
        const int b0 = win0 >> 8;

        // ---- stage 1: load + transpose inputs ----
        {
            const float* pg = pressure + (size_t)win0 * 120;
            for (int i = tid; i < 960; i += 512) {
                int w8 = i / 120, r = i - w8 * 120, w = r / 6, c = r - w * 6;
                s[OFF_XP + w8 * 120 + c * 20 + w] = pg[i];
            }
            const float* tg = torque + (size_t)win0 * 240;
            for (int i = tid; i < 1920; i += 512) {
                int w8 = i / 240, r = i - w8 * 240, w = r / 12, c = r - w * 12;
                s[OFF_XT + w8 * 240 + c * 20 + w] = tg[i];
            }
        }
        __syncthreads();

        // ---- stage 2: conv1 + relu ----
        {
            const int o = lane;
            float acc[18];
            if (enc == 0) {
                #pragma unroll
                for (int l = 0; l < 18; l++) acc[l] = s[OFF_B1P + o];
                const float* xb = s + OFF_XP + wn * 120;
                #pragma unroll
                for (int ci = 0; ci < 6; ci++) {
                    float4 w = *(const float4*)(s + OFF_W1P + (ci * 32 + o) * 4);
                    float x[20];
                    #pragma unroll
                    for (int q = 0; q < 5; q++) {
                        float4 v = *(const float4*)(xb + ci * 20 + q * 4);
                        x[q*4] = v.x; x[q*4+1] = v.y; x[q*4+2] = v.z; x[q*4+3] = v.w;
                    }
                    #pragma unroll
                    for (int l = 0; l < 18; l++)
                        acc[l] += w.x * x[l] + w.y * x[l+1] + w.z * x[l+2];
                }
            } else {
                #pragma unroll
                for (int l = 0; l < 18; l++) acc[l] = s[OFF_B1T + o];
                const float* xb = s + OFF_XT + wn * 240;
                #pragma unroll
                for (int ci = 0; ci < 12; ci++) {
                    float4 w = *(const float4*)(s + OFF_W1T + (ci * 32 + o) * 4);
                    float x[20];
                    #pragma unroll
                    for (int q = 0; q < 5; q++) {
                        float4 v = *(const float4*)(xb + ci * 20 + q * 4);
                        x[q*4] = v.x; x[q*4+1] = v.y; x[q*4+2] = v.z; x[q*4+3] = v.w;
                    }
                    #pragma unroll
                    for (int l = 0; l < 18; l++)
                        acc[l] += w.x * x[l] + w.y * x[l+1] + w.z * x[l+2];
                }
            }
            float* hb = s + OFF_H1 + wn * 1280 + enc * 640 + o * 20;
            #pragma unroll
            for (int l = 0; l < 18; l += 2) {
                float2 v;
                v.x = fmaxf(acc[l],   0.f);
                v.y = fmaxf(acc[l+1], 0.f);
                *(float2*)(hb + l) = v;
            }
        }
        __syncthreads();

        // ---- stage 3: conv2 + relu + mean pool ----
        {
            const int o = lane;
            float acc[16];
            #pragma unroll
            for (int l = 0; l < 16; l++) acc[l] = s[OFF_B2 + enc * 32 + o];
            const float* hbase = s + OFF_H1 + wn * 1280 + enc * 640;
            const float* wbase = s + OFF_W2P + enc * 4096;
            #pragma unroll 4
            for (int ci = 0; ci < 32; ci++) {
                float4 w = *(const float4*)(wbase + (ci * 32 + o) * 4);
                const float* hr = hbase + ci * 20;
                float x[18];
                #pragma unroll
                for (int q = 0; q < 4; q++) {
                    float4 v = *(const float4*)(hr + q * 4);
                    x[q*4] = v.x; x[q*4+1] = v.y; x[q*4+2] = v.z; x[q*4+3] = v.w;
                }
                { float2 v = *(const float2*)(hr + 16); x[16] = v.x; x[17] = v.y; }
                #pragma unroll
                for (int l = 0; l < 16; l++)
                    acc[l] += w.x * x[l] + w.y * x[l+1] + w.z * x[l+2];
            }
            float pool = 0.f;
            #pragma unroll
            for (int l = 0; l < 16; l++) pool += fmaxf(acc[l], 0.f);
            s[OFF_CAT + wn * 80 + enc * 32 + o] = pool * (1.f / 16.f);
        }
        if (tid < 64) {
            int w8 = tid >> 3, k = tid & 7;
            s[OFF_CAT + w8 * 80 + 64 + k] =
                fmaxf(frag[b0] * s[OFF_FW + k] + s[OFF_FB + k], 0.f);
        }
        __syncthreads();

        // ---- stage 4: projection + relu (weights from global, coalesced) ----
        {
            const int w8 = tid >> 6, o = tid & 63;
            float acc = __ldg(prb + o);
            const float* cat = s + OFF_CAT + w8 * 80;
            #pragma unroll
            for (int j = 0; j < 72; j++)
                acc += __ldg(g_prwT + j * 64 + o) * cat[j];
            s[OFF_FEAT + w8 * 64 + o] = fmaxf(acc, 0.f);
        }
        __syncthreads();

        // ---- stage 5: xg = feat @ Wih.T + bias (weights from global) ----
        {
            const int w8 = tid >> 6, g0 = (tid & 63) * 4;
            const float* ft = s + OFF_FEAT + w8 * 64;
            float4 acc = *(const float4*)(g_bsum + g0);
            #pragma unroll
            for (int h = 0; h < 64; h++) {
                float f = ft[h];
                float4 w = __ldg((const float4*)(g_WihT + h * 256 + g0));
                acc.x += w.x * f; acc.y += w.y * f;
                acc.z += w.z * f; acc.w += w.w * f;
            }
            *(float4*)(g_xg + (size_t)(win0 + w8) * 256 + g0) = acc;
        }
        __syncthreads();
    }
}

// ---------------------------------------------------------------------------
// Kernel B: per-batch LSTM (head deferred). tanh.approx activations.
// ---------------------------------------------------------------------------
__global__ __launch_bounds__(256) void lstm_kernel(
    const float* __restrict__ Whh, float* __restrict__ out)
{
    __shared__ __align__(16) float h_s[64];
    __shared__ float gates[256];

    const int b = blockIdx.x;
    const int j = threadIdx.x;

    ulonglong2 wv[16];
    const ulonglong2* wr = reinterpret_cast<const ulonglong2*>(Whh + j * 64);
    #pragma unroll
    for (int q = 0; q < 16; q++) wv[q] = wr[q];

    if (j < 64) h_s[j] = 0.f;
    float c = 0.f;

    const float* xg = g_xg + (size_t)b * T_ * 256;
    float xcur = xg[j];
    __syncthreads();

    for (int t = 0; t < T_; t++) {
        float xnext = (t + 1 < T_) ? xg[(size_t)(t + 1) * 256 + j] : 0.f;

        unsigned long long a0 = 0ull, a1 = 0ull;
        const ulonglong2* h2 = reinterpret_cast<const ulonglong2*>(h_s);
        #pragma unroll
        for (int q = 0; q < 16; q++) {
            ulonglong2 hh = h2[q];
            a0 = fma2(wv[q].x, hh.x, a0);
            a1 = fma2(wv[q].y, hh.y, a1);
        }
        float2 p0 = u2f2(a0), p1 = u2f2(a1);
        gates[j] = xcur + (p0.x + p0.y) + (p1.x + p1.y);
        xcur = xnext;
        __syncthreads();

        if (j < 64) {
            float gi = gates[j],       gf = gates[64 + j];
            float gg = gates[128 + j], go = gates[192 + j];
            c = siga(gf) * c + siga(gi) * tanha(gg);
            float h = siga(go) * tanha(c);
            h_s[j] = h;
            g_h[((size_t)b * T_ + t) * 64 + j] = h;
        }
        __syncthreads();
    }

    if (j < 64) {
        out[(size_t)B_ * T_ * 4 + b * 64 + j] = h_s[j];                 // hT
        out[(size_t)B_ * T_ * 4 + B_ * 64 + b * 64 + j] = c;            // cT
    }
}

// ---------------------------------------------------------------------------
// Kernel C: head
// ---------------------------------------------------------------------------
__global__ __launch_bounds__(256) void head_kernel(
    const float* __restrict__ hw, const float* __restrict__ hb,
    float* __restrict__ out)
{
    __shared__ float s_hw[256];
    __shared__ float s_hb[4];
    const int tid = threadIdx.x;
    s_hw[tid] = hw[tid];
    if (tid < 4) s_hb[tid] = hb[tid];
    __syncthreads();

    const int bt = blockIdx.x * 256 + tid;
    const float4* h4 = reinterpret_cast<const float4*>(g_h + (size_t)bt * 64);
    float a0 = s_hb[0], a1 = s_hb[1], a2 = s_hb[2], a3 = s_hb[3];
    #pragma unroll
    for (int q = 0; q < 16; q++) {
        float4 hv = h4[q];
        a0 += s_hw[      q*4]*hv.x + s_hw[      q*4+1]*hv.y + s_hw[      q*4+2]*hv.z + s_hw[      q*4+3]*hv.w;
        a1 += s_hw[ 64 + q*4]*hv.x + s_hw[ 64 + q*4+1]*hv.y + s_hw[ 64 + q*4+2]*hv.z + s_hw[ 64 + q*4+3]*hv.w;
        a2 += s_hw[128 + q*4]*hv.x + s_hw[128 + q*4+1]*hv.y + s_hw[128 + q*4+2]*hv.z + s_hw[128 + q*4+3]*hv.w;
        a3 += s_hw[192 + q*4]*hv.x + s_hw[192 + q*4+1]*hv.y + s_hw[192 + q*4+2]*hv.z + s_hw[192 + q*4+3]*hv.w;
    }
    float4 r;
    r.x = siga(a0); r.y = siga(a1); r.z = siga(a2); r.w = siga(a3);
    *reinterpret_cast<float4*>(out + (size_t)bt * 4) = r;
}

// ---------------------------------------------------------------------------
extern "C" void kernel_launch(void* const* d_in, const int* in_sizes, int n_in,
                              void* d_out, int out_size)
{
    const float* pressure = (const float*)d_in[0];
    const float* torque   = (const float*)d_in[1];
    const float* frag     = (const float*)d_in[2];
    const float* pw1 = (const float*)d_in[3];
    const float* pb1 = (const float*)d_in[4];
    const float* pw2 = (const float*)d_in[5];
    const float* pb2 = (const float*)d_in[6];
    const float* tw1 = (const float*)d_in[7];
    const float* tb1 = (const float*)d_in[8];
    const float* tw2 = (const float*)d_in[9];
    const float* tb2 = (const float*)d_in[10];
    const float* fw  = (const float*)d_in[11];
    const float* fb  = (const float*)d_in[12];
    const float* prw = (const float*)d_in[13];
    const float* prb = (const float*)d_in[14];
    const float* Wih = (const float*)d_in[15];
    const float* Whh = (const float*)d_in[16];
    const float* bih = (const float*)d_in[17];
    const float* bhh = (const float*)d_in[18];
    const float* hw  = (const float*)d_in[19];
    const float* hb  = (const float*)d_in[20];

    const int smem_bytes = SMEM_FLOATS * sizeof(float);   // 99648 B
    cudaFuncSetAttribute(encode_kernel,
                         cudaFuncAttributeMaxDynamicSharedMemorySize, smem_bytes);

    init_kernel<<<64, 256>>>(prw, Wih, bih, bhh);
    encode_kernel<<<304, 512, smem_bytes>>>(
        pressure, torque, frag,
        pw1, pb1, pw2, pb2, tw1, tb1, tw2, tb2,
        fw, fb, prb);
    lstm_kernel<<<B_, 256>>>(Whh, (float*)d_out);
    head_kernel<<<64, 256>>>(hw, hb, (float*)d_out);
}

// round 5
// speedup vs baseline: 3.1571x; 1.0388x over previous
#include <cuda_runtime.h>
#include <math.h>

#define B_   64
#define T_   256
#define W_   20
#define NP   6
#define NT   12
#define CC   32
#define FD   8
#define PR   64
#define NW   (B_*T_)      // 16384 windows
#define WB   8            // windows per CTA iteration (4 pairs)
#define NCHUNK (NW / WB)  // 2048

typedef unsigned long long ull;

// scratch (static device arrays — no allocs)
__device__ float g_xg[NW * 4 * PR];   // precomputed input gates
__device__ float g_h [NW * PR];       // per-step hidden states
__device__ float g_prwT[72 * 64];     // projection weights, transposed
__device__ float g_WihT[64 * 256];    // Wih transposed [h][g]
__device__ float g_bsum[256];         // bih + bhh

// ---------------------------------------------------------------------------
// fast math helpers
// ---------------------------------------------------------------------------
__device__ __forceinline__ ull fma2(ull a, ull b, ull c) {
    ull d;
    asm("fma.rn.f32x2 %0, %1, %2, %3;" : "=l"(d) : "l"(a), "l"(b), "l"(c));
    return d;
}
__device__ __forceinline__ float2 u2f2(ull v) {
    float2 r;
    asm("mov.b64 {%0, %1}, %2;" : "=f"(r.x), "=f"(r.y) : "l"(v));
    return r;
}
__device__ __forceinline__ ull pack2(float a, float b) {
    ull r;
    asm("mov.b64 %0, {%1, %2};" : "=l"(r) : "f"(a), "f"(b));
    return r;
}
__device__ __forceinline__ float tanha(float x) {
    float y;
    asm("tanh.approx.f32 %0, %1;" : "=f"(y) : "f"(x));
    return y;
}
__device__ __forceinline__ float siga(float x) {
    return fmaf(tanha(0.5f * x), 0.5f, 0.5f);
}

// ---------------------------------------------------------------------------
// smem layout (floats) — 24912 floats = 99648 B  (2 CTAs/SM)
// window-pair interleaved layouts: [...][2] last dim = window-in-pair
// ---------------------------------------------------------------------------
#define OFF_W1P   0                    // [6ci][32o][4(k pad)]
#define OFF_W1T   (OFF_W1P + 768)      // [12][32][4]
#define OFF_B1P   (OFF_W1T + 1536)     // 32
#define OFF_B1T   (OFF_B1P + 32)       // 32
#define OFF_W2P   (OFF_B1T + 32)       // [2enc][32ci][32o][4]
#define OFF_B2    (OFF_W2P + 8192)     // [2][32]
#define OFF_FW    (OFF_B2  + 64)       // 8
#define OFF_FB    (OFF_FW  + 8)        // 8
#define OFF_XPI   (OFF_FB  + 8)        // [4p][6c][20w][2]  = 960
#define OFF_XTI   (OFF_XPI + 960)      // [4p][12c][20w][2] = 1920
#define OFF_H1I   (OFF_XTI + 1920)     // [4p][2enc][32c][20l][2] = 10240
#define OFF_CATI  (OFF_H1I + 10240)    // [4p][80j][2] = 640
#define OFF_FEATI (OFF_CATI+ 640)      // [4p][64h][2] = 512
#define SMEM_FLOATS (OFF_FEATI + 512)  // 24912

// ---------------------------------------------------------------------------
// Kernel 0: weight transposes
// ---------------------------------------------------------------------------
__global__ __launch_bounds__(256) void init_kernel(
    const float* __restrict__ prw, const float* __restrict__ Wih,
    const float* __restrict__ bih, const float* __restrict__ bhh)
{
    int i = blockIdx.x * 256 + threadIdx.x;
    if (i < 4608) { int j = i >> 6, o = i & 63; g_prwT[i] = prw[o * 72 + j]; }
    if (i < 16384) { int h = i >> 8, g = i & 255; g_WihT[i] = Wih[g * 64 + h]; }
    if (i < 256) g_bsum[i] = bih[i] + bhh[i];
}

// ---------------------------------------------------------------------------
// Kernel A: encoders (packed f32x2 over window pairs) + projection + xg
// ---------------------------------------------------------------------------
__global__ __launch_bounds__(512, 2) void encode_kernel(
    const float* __restrict__ pressure, const float* __restrict__ torque,
    const float* __restrict__ frag,
    const float* __restrict__ pw1, const float* __restrict__ pb1,
    const float* __restrict__ pw2, const float* __restrict__ pb2,
    const float* __restrict__ tw1, const float* __restrict__ tb1,
    const float* __restrict__ tw2, const float* __restrict__ tb2,
    const float* __restrict__ fw,  const float* __restrict__ fb,
    const float* __restrict__ prb)
{
    extern __shared__ float s[];
    const int tid = threadIdx.x;

    // ---- weight staging ----
    for (int i = tid; i < 576; i += 512) {              // pw1[o][ci][k]
        int o = i / 18, r = i - o * 18, ci = r / 3, k = r - ci * 3;
        s[OFF_W1P + (ci * 32 + o) * 4 + k] = pw1[i];
    }
    for (int i = tid; i < 1152; i += 512) {             // tw1[o][ci][k]
        int o = i / 36, r = i - o * 36, ci = r / 3, k = r - ci * 3;
        s[OFF_W1T + (ci * 32 + o) * 4 + k] = tw1[i];
    }
    for (int i = tid; i < 3072; i += 512) {             // pw2/tw2 [o][ci][k]
        int o = i / 96, r = i - o * 96, ci = r / 3, k = r - ci * 3;
        s[OFF_W2P +        (ci * 32 + o) * 4 + k] = pw2[i];
        s[OFF_W2P + 4096 + (ci * 32 + o) * 4 + k] = tw2[i];
    }
    for (int i = tid; i < 32; i += 512) {
        s[OFF_B1P + i] = pb1[i]; s[OFF_B1T + i] = tb1[i];
        s[OFF_B2  + i] = pb2[i]; s[OFF_B2 + 32 + i] = tb2[i];
    }
    if (tid < 8) { s[OFF_FW + tid] = fw[tid]; s[OFF_FB + tid] = fb[tid]; }
    __syncthreads();

    const int wid = tid >> 5, lane = tid & 31;
    const int p = wid & 3, enc = wid >> 2;   // valid for wid < 8

    for (int chunk = blockIdx.x; chunk < NCHUNK; chunk += gridDim.x) {
        const int win0 = chunk * WB;
        const int b0 = win0 >> 8;

        // ---- stage 1: load + transpose inputs into window-pair layout ----
        {
            const float* pg = pressure + (size_t)win0 * 120;
            for (int i = tid; i < 960; i += 512) {
                int w8 = i / 120, r = i - w8 * 120, w = r / 6, c = r - w * 6;
                s[OFF_XPI + (w8 >> 1) * 240 + (c * 20 + w) * 2 + (w8 & 1)] = pg[i];
            }
            const float* tg = torque + (size_t)win0 * 240;
            for (int i = tid; i < 1920; i += 512) {
                int w8 = i / 240, r = i - w8 * 240, w = r / 12, c = r - w * 12;
                s[OFF_XTI + (w8 >> 1) * 480 + (c * 20 + w) * 2 + (w8 & 1)] = tg[i];
            }
        }
        __syncthreads();

        // ---- stage 2: conv1 + relu (packed pairs; warps 0-7) ----
        if (wid < 8) {
            const int o = lane;
            ull acc[18];
            if (enc == 0) {
                ull bb = pack2(s[OFF_B1P + o], s[OFF_B1P + o]);
                #pragma unroll
                for (int l = 0; l < 18; l++) acc[l] = bb;
                const ull* xp = (const ull*)(s + OFF_XPI + p * 240);
                #pragma unroll
                for (int ci = 0; ci < 6; ci++) {
                    float4 w = *(const float4*)(s + OFF_W1P + (ci * 32 + o) * 4);
                    ull wx = pack2(w.x, w.x), wy = pack2(w.y, w.y), wz = pack2(w.z, w.z);
                    const ull* xr = xp + ci * 20;
                    ull p0 = xr[0], p1 = xr[1];
                    #pragma unroll
                    for (int l = 0; l < 18; l++) {
                        ull p2 = xr[l + 2];
                        acc[l] = fma2(wx, p0, acc[l]);
                        acc[l] = fma2(wy, p1, acc[l]);
                        acc[l] = fma2(wz, p2, acc[l]);
                        p0 = p1; p1 = p2;
                    }
                }
            } else {
                ull bb = pack2(s[OFF_B1T + o], s[OFF_B1T + o]);
                #pragma unroll
                for (int l = 0; l < 18; l++) acc[l] = bb;
                const ull* xp = (const ull*)(s + OFF_XTI + p * 480);
                #pragma unroll
                for (int ci = 0; ci < 12; ci++) {
                    float4 w = *(const float4*)(s + OFF_W1T + (ci * 32 + o) * 4);
                    ull wx = pack2(w.x, w.x), wy = pack2(w.y, w.y), wz = pack2(w.z, w.z);
                    const ull* xr = xp + ci * 20;
                    ull p0 = xr[0], p1 = xr[1];
                    #pragma unroll
                    for (int l = 0; l < 18; l++) {
                        ull p2 = xr[l + 2];
                        acc[l] = fma2(wx, p0, acc[l]);
                        acc[l] = fma2(wy, p1, acc[l]);
                        acc[l] = fma2(wz, p2, acc[l]);
                        p0 = p1; p1 = p2;
                    }
                }
            }
            float2* hb = (float2*)(s + OFF_H1I) + ((p * 2 + enc) * 32 + o) * 20;
            #pragma unroll
            for (int l = 0; l < 18; l++) {
                float2 v = u2f2(acc[l]);
                v.x = fmaxf(v.x, 0.f); v.y = fmaxf(v.y, 0.f);
                hb[l] = v;
            }
        }
        __syncthreads();

        // ---- stage 3: conv2 + relu + mean pool (packed pairs; warps 0-7) ----
        if (wid < 8) {
            const int o = lane;
            float bv = s[OFF_B2 + enc * 32 + o];
            ull bb = pack2(bv, bv);
            ull acc[16];
            #pragma unroll
            for (int l = 0; l < 16; l++) acc[l] = bb;
            const ull* hp = (const ull*)(s + OFF_H1I + (p * 2 + enc) * 1280);
            const float* wbase = s + OFF_W2P + enc * 4096;
            #pragma unroll 4
            for (int ci = 0; ci < 32; ci++) {
                float4 w = *(const float4*)(wbase + (ci * 32 + o) * 4);
                ull wx = pack2(w.x, w.x), wy = pack2(w.y, w.y), wz = pack2(w.z, w.z);
                const ull* hr = hp + ci * 20;
                ull p0 = hr[0], p1 = hr[1];
                #pragma unroll
                for (int l = 0; l < 16; l++) {
                    ull p2 = hr[l + 2];
                    acc[l] = fma2(wx, p0, acc[l]);
                    acc[l] = fma2(wy, p1, acc[l]);
                    acc[l] = fma2(wz, p2, acc[l]);
                    p0 = p1; p1 = p2;
                }
            }
            float s0 = 0.f, s1 = 0.f;
            #pragma unroll
            for (int l = 0; l < 16; l++) {
                float2 v = u2f2(acc[l]);
                s0 += fmaxf(v.x, 0.f); s1 += fmaxf(v.y, 0.f);
            }
            float2 pv; pv.x = s0 * (1.f / 16.f); pv.y = s1 * (1.f / 16.f);
            ((float2*)(s + OFF_CATI))[p * 80 + enc * 32 + o] = pv;
        }
        if (tid < 32) {     // fragility (same value for both windows of a pair)
            int pp = tid >> 3, k = tid & 7;
            float v = fmaxf(frag[b0] * s[OFF_FW + k] + s[OFF_FB + k], 0.f);
            float2 pv; pv.x = v; pv.y = v;
            ((float2*)(s + OFF_CATI))[pp * 80 + 64 + k] = pv;
        }
        __syncthreads();

        // ---- stage 4: projection + relu (all 512 threads, scalar) ----
        {
            const int w8 = tid >> 6, o = tid & 63;
            const int pp = w8 >> 1, wl = w8 & 1;
            float acc = __ldg(prb + o);
            const float* cat = s + OFF_CATI + pp * 160 + wl;
            #pragma unroll
            for (int j = 0; j < 72; j++)
                acc += __ldg(g_prwT + j * 64 + o) * cat[j * 2];
            s[OFF_FEATI + (pp * 64 + o) * 2 + wl] = fmaxf(acc, 0.f);
        }
        __syncthreads();

        // ---- stage 5: xg = feat @ Wih.T + bias ----
        {
            const int w8 = tid >> 6, g0 = (tid & 63) * 4;
            const int pp = w8 >> 1, wl = w8 & 1;
            const float* ft = s + OFF_FEATI + pp * 128 + wl;
            float4 acc = *(const float4*)(g_bsum + g0);
            #pragma unroll
            for (int h = 0; h < 64; h++) {
                float f = ft[h * 2];
                float4 w = __ldg((const float4*)(g_WihT + h * 256 + g0));
                acc.x += w.x * f; acc.y += w.y * f;
                acc.z += w.z * f; acc.w += w.w * f;
            }
            *(float4*)(g_xg + (size_t)(win0 + w8) * 256 + g0) = acc;
        }
        __syncthreads();
    }
}

// ---------------------------------------------------------------------------
// Kernel B: per-batch LSTM (head deferred). tanh.approx activations.
// ---------------------------------------------------------------------------
__global__ __launch_bounds__(256) void lstm_kernel(
    const float* __restrict__ Whh, float* __restrict__ out)
{
    __shared__ __align__(16) float h_s[64];
    __shared__ float gates[256];

    const int b = blockIdx.x;
    const int j = threadIdx.x;

    ulonglong2 wv[16];
    const ulonglong2* wr = reinterpret_cast<const ulonglong2*>(Whh + j * 64);
    #pragma unroll
    for (int q = 0; q < 16; q++) wv[q] = wr[q];

    if (j < 64) h_s[j] = 0.f;
    float c = 0.f;

    const float* xg = g_xg + (size_t)b * T_ * 256;
    float xcur = xg[j];
    __syncthreads();

    for (int t = 0; t < T_; t++) {
        float xnext = (t + 1 < T_) ? xg[(size_t)(t + 1) * 256 + j] : 0.f;

        ull a0 = 0ull, a1 = 0ull;
        const ulonglong2* h2 = reinterpret_cast<const ulonglong2*>(h_s);
        #pragma unroll
        for (int q = 0; q < 16; q++) {
            ulonglong2 hh = h2[q];
            a0 = fma2(wv[q].x, hh.x, a0);
            a1 = fma2(wv[q].y, hh.y, a1);
        }
        float2 p0 = u2f2(a0), p1 = u2f2(a1);
        gates[j] = xcur + (p0.x + p0.y) + (p1.x + p1.y);
        xcur = xnext;
        __syncthreads();

        if (j < 64) {
            float gi = gates[j],       gf = gates[64 + j];
            float gg = gates[128 + j], go = gates[192 + j];
            c = siga(gf) * c + siga(gi) * tanha(gg);
            float h = siga(go) * tanha(c);
            h_s[j] = h;
            g_h[((size_t)b * T_ + t) * 64 + j] = h;
        }
        __syncthreads();
    }

    if (j < 64) {
        out[(size_t)B_ * T_ * 4 + b * 64 + j] = h_s[j];                 // hT
        out[(size_t)B_ * T_ * 4 + B_ * 64 + b * 64 + j] = c;            // cT
    }
}

// ---------------------------------------------------------------------------
// Kernel C: head
// ---------------------------------------------------------------------------
__global__ __launch_bounds__(256) void head_kernel(
    const float* __restrict__ hw, const float* __restrict__ hb,
    float* __restrict__ out)
{
    __shared__ float s_hw[256];
    __shared__ float s_hb[4];
    const int tid = threadIdx.x;
    s_hw[tid] = hw[tid];
    if (tid < 4) s_hb[tid] = hb[tid];
    __syncthreads();

    const int bt = blockIdx.x * 256 + tid;
    const float4* h4 = reinterpret_cast<const float4*>(g_h + (size_t)bt * 64);
    float a0 = s_hb[0], a1 = s_hb[1], a2 = s_hb[2], a3 = s_hb[3];
    #pragma unroll
    for (int q = 0; q < 16; q++) {
        float4 hv = h4[q];
        a0 += s_hw[      q*4]*hv.x + s_hw[      q*4+1]*hv.y + s_hw[      q*4+2]*hv.z + s_hw[      q*4+3]*hv.w;
        a1 += s_hw[ 64 + q*4]*hv.x + s_hw[ 64 + q*4+1]*hv.y + s_hw[ 64 + q*4+2]*hv.z + s_hw[ 64 + q*4+3]*hv.w;
        a2 += s_hw[128 + q*4]*hv.x + s_hw[128 + q*4+1]*hv.y + s_hw[128 + q*4+2]*hv.z + s_hw[128 + q*4+3]*hv.w;
        a3 += s_hw[192 + q*4]*hv.x + s_hw[192 + q*4+1]*hv.y + s_hw[192 + q*4+2]*hv.z + s_hw[192 + q*4+3]*hv.w;
    }
    float4 r;
    r.x = siga(a0); r.y = siga(a1); r.z = siga(a2); r.w = siga(a3);
    *reinterpret_cast<float4*>(out + (size_t)bt * 4) = r;
}

// ---------------------------------------------------------------------------
extern "C" void kernel_launch(void* const* d_in, const int* in_sizes, int n_in,
                              void* d_out, int out_size)
{
    const float* pressure = (const float*)d_in[0];
    const float* torque   = (const float*)d_in[1];
    const float* frag     = (const float*)d_in[2];
    const float* pw1 = (const float*)d_in[3];
    const float* pb1 = (const float*)d_in[4];
    const float* pw2 = (const float*)d_in[5];
    const float* pb2 = (const float*)d_in[6];
    const float* tw1 = (const float*)d_in[7];
    const float* tb1 = (const float*)d_in[8];
    const float* tw2 = (const float*)d_in[9];
    const float* tb2 = (const float*)d_in[10];
    const float* fw  = (const float*)d_in[11];
    const float* fb  = (const float*)d_in[12];
    const float* prw = (const float*)d_in[13];
    const float* prb = (const float*)d_in[14];
    const float* Wih = (const float*)d_in[15];
    const float* Whh = (const float*)d_in[16];
    const float* bih = (const float*)d_in[17];
    const float* bhh = (const float*)d_in[18];
    const float* hw  = (const float*)d_in[19];
    const float* hb  = (const float*)d_in[20];

    const int smem_bytes = SMEM_FLOATS * sizeof(float);   // 99648 B
    cudaFuncSetAttribute(encode_kernel,
                         cudaFuncAttributeMaxDynamicSharedMemorySize, smem_bytes);

    init_kernel<<<64, 256>>>(prw, Wih, bih, bhh);
    encode_kernel<<<304, 512, smem_bytes>>>(
        pressure, torque, frag,
        pw1, pb1, pw2, pb2, tw1, tb1, tw2, tb2,
        fw, fb, prb);
    lstm_kernel<<<B_, 256>>>(Whh, (float*)d_out);
    head_kernel<<<64, 256>>>(hw, hb, (float*)d_out);
}